// round 11
// baseline (speedup 1.0000x reference)
#include <cuda_runtime.h>
#include <cuda_bf16.h>
#include <cstdint>

// Problem dims (fixed by reference setup_inputs)
#define B_   4
#define N_   32
#define R_   64
#define H_   480
#define W_   640
#define HW_  (H_ * W_)         // 307200
#define NVEC (HW_ / 4)         // 76800 float4 per (b,n) slice
#define BN_  (B_ * N_)         // 128
#define BR_  (B_ * R_)         // 256

#define NGRP    8                    // n-values per block
#define GROUPS  (B_ * N_ / NGRP)     // 16
#define CHUNKS  37                   // 16*37 = 592 = 4*148 blocks, one balanced wave
#define NBLOCKS (GROUPS * CHUNKS)
#define NTHR    384                  // 12 warps; 4 blocks/SM -> 48 warps (75% of 64)

#define T_F4        192              // float4 per array per tile (3KB); 768 floats = 384 f2
#define NARR        (NGRP + 1)       // 8 masks + 1 depth
#define STAGES      2
#define TILE_F4     (NARR * T_F4)    // 1728 float4 per stage
#define TILE_BYTES  (TILE_F4 * 16)   // 27648 per stage; x2 stages = 54KB

#define MARGIN_RANK 0.1f
#define MARGIN_OCC  0.3f
#define LAMBDA_OCC  1.5f
#define MIN_PIXELS  20.0f

// Per-(chunk, bn) partials — each block owns its slots, no atomics needed.
__device__ float g_ps[CHUNKS * BN_];
__device__ float g_pc[CHUNKS * BN_];
__device__ unsigned int g_ctr = 0;   // last-block-done counter (self-resetting)

__device__ __forceinline__ uint32_t smem_u32(const void* p) {
    return (uint32_t)__cvta_generic_to_shared(p);
}
__device__ __forceinline__ void cp_async16(uint32_t dst, const void* src) {
    asm volatile("cp.async.cg.shared.global [%0], [%1], 16;\n" :: "r"(dst), "l"(src));
}
#define CP_COMMIT() asm volatile("cp.async.commit_group;\n" ::: "memory")
#define CP_WAIT(n)  asm volatile("cp.async.wait_group %0;\n" :: "n"(n) : "memory")

__global__ void __launch_bounds__(NTHR, 4) fused_kernel(
    const float* __restrict__ depth,   // [B,1,H,W]
    const float* __restrict__ masks,   // [B,N,H,W]
    const int*   __restrict__ subj,
    const int*   __restrict__ obj,
    const int*   __restrict__ rel,
    const float* __restrict__ conf,
    float*       __restrict__ out)
{
    // Pipeline smem: [stage][array][T_F4] float4; array 0..7 = masks, 8 = depth
    __shared__ float4 tile[STAGES * TILE_F4];    // 54 KB

    const int tid   = threadIdx.x;
    const int bx    = blockIdx.x;          // 0..591
    const int chunk = bx % CHUNKS;
    const int grp   = bx / CHUNKS;         // 0..15
    const int b     = grp >> 2;            // 4 groups per batch
    const int n0    = (grp & 3) * NGRP;

    const float4* __restrict__ dp = reinterpret_cast<const float4*>(depth)
                                    + (size_t)b * NVEC;
    const float4* __restrict__ mp = reinterpret_cast<const float4*>(masks)
                                    + (size_t)(b * N_ + n0) * NVEC;

    const uint32_t tile0 = smem_u32(&tile[0]);

    // Chunk range in float4 units (balanced within +-1 f4 across chunks)
    const int c0 = (int)(((long long)chunk       * NVEC) / CHUNKS);
    const int c1 = (int)(((long long)(chunk + 1) * NVEC) / CHUNKS);
    const int nt = (c1 - c0 + T_F4 - 1) / T_F4;    // 11 tiles (10 full + partial)

    float s[NGRP], c[NGRP];
    #pragma unroll
    for (int j = 0; j < NGRP; ++j) { s[j] = 0.0f; c[j] = 0.0f; }

    // ---- cp.async one (possibly partial) tile into a stage ----
    // Slots: 1728 total, thread handles slot tid + j*384, j=0..4 (j=4 partial coverage)
    auto issue = [&](int stage, int t) {
        const int f4off = c0 + t * T_F4;
        const int nf4   = min(T_F4, c1 - f4off);
        const uint32_t base = tile0 + (uint32_t)stage * TILE_BYTES;
        #pragma unroll
        for (int j = 0; j < 5; ++j) {
            const int slot = tid + j * NTHR;
            if (slot < TILE_F4) {
                const int a = slot / T_F4;
                const int e = slot - a * T_F4;
                if (e < nf4) {
                    const float4* src = (a < NGRP)
                        ? (mp + (size_t)a * NVEC + f4off + e)
                        : (dp + f4off + e);
                    cp_async16(base + (uint32_t)slot * 16u, src);
                }
            }
        }
    };

    // Prologue
    #pragma unroll
    for (int k = 0; k < STAGES; ++k) {
        if (k < nt) issue(k, k);
        CP_COMMIT();
    }

    // Main pipeline
    for (int k = 0; k < nt; ++k) {
        const int st = k & (STAGES - 1);
        CP_WAIT(STAGES - 1);
        __syncthreads();

        const int nf4 = min(T_F4, c1 - (c0 + k * T_F4));
        if (tid < nf4 * 2) {
            // Each thread owns float2 lane tid of the 768-float arrays
            const float2* dt2 = reinterpret_cast<const float2*>(
                &tile[st * TILE_F4 + NGRP * T_F4]);
            const float2  d   = dt2[tid];
            #pragma unroll
            for (int j = 0; j < NGRP; ++j) {
                const float2* mt2 = reinterpret_cast<const float2*>(
                    &tile[st * TILE_F4 + j * T_F4]);
                float2 m = mt2[tid];
                if (m.x > 0.5f) { s[j] += d.x; c[j] += 1.0f; }
                if (m.y > 0.5f) { s[j] += d.y; c[j] += 1.0f; }
            }
        }
        __syncthreads();

        if (k + STAGES < nt) issue(st, k + STAGES);
        CP_COMMIT();
    }

    // ---- reduce the 16 accumulators across the block (12 warps) ----
    #pragma unroll
    for (int j = 0; j < NGRP; ++j) {
        #pragma unroll
        for (int off = 16; off > 0; off >>= 1) {
            s[j] += __shfl_xor_sync(0xFFFFFFFFu, s[j], off);
            c[j] += __shfl_xor_sync(0xFFFFFFFFu, c[j], off);
        }
    }

    __shared__ float sh[12][2 * NGRP];      // [warp][16 values]
    const int lane = tid & 31;
    const int wid  = tid >> 5;
    if (lane == 0) {
        #pragma unroll
        for (int j = 0; j < NGRP; ++j) {
            sh[wid][j]        = s[j];
            sh[wid][NGRP + j] = c[j];
        }
    }
    __syncthreads();

    if (tid < 2 * NGRP) {
        float v = 0.0f;
        #pragma unroll
        for (int w = 0; w < 12; ++w) v += sh[w][tid];
        const int j  = tid & (NGRP - 1);
        const int bn = b * N_ + n0 + j;
        if (tid < NGRP) g_ps[chunk * BN_ + bn] = v;
        else            g_pc[chunk * BN_ + bn] = v;
    }

    // ---- last-block-done: the final block runs the epilogue ----
    __shared__ bool is_last;
    __threadfence();
    __syncthreads();
    if (tid == 0) {
        unsigned int prev = atomicAdd(&g_ctr, 1u);
        is_last = (prev == NBLOCKS - 1);
    }
    __syncthreads();
    if (!is_last) return;
    __threadfence();

    // ===================== epilogue (one block; 256 of 384 threads active) =====================
    __shared__ float sh_mean[BN_], sh_cnt[BN_];
    if (tid < BN_) {
        float sAcc = 0.0f, cAcc = 0.0f;
        #pragma unroll
        for (int ch = 0; ch < CHUNKS; ++ch) {
            sAcc += g_ps[ch * BN_ + tid];
            cAcc += g_pc[ch * BN_ + tid];
        }
        sh_mean[tid] = sAcc / fmaxf(cAcc, 1.0f);
        sh_cnt[tid]  = cAcc;
    }
    __syncthreads();

    float total = 0.0f, count = 0.0f;
    if (tid < BR_) {
        const int bb_ = tid / R_;
        const int rt = rel[tid];
        const int si = subj[tid];
        const int oi = obj[tid];
        const int a  = (rt == 1) ? oi : si;
        const int bo = (rt == 1) ? si : oi;

        const float cntA = sh_cnt[bb_ * N_ + a];
        const float cntB = sh_cnt[bb_ * N_ + bo];
        const float dA   = sh_mean[bb_ * N_ + a];
        const float dB   = sh_mean[bb_ * N_ + bo];
        const bool  valid = (cntA >= MIN_PIXELS) && (cntB >= MIN_PIXELS);

        const float margin = (rt == 2) ? MARGIN_OCC : MARGIN_RANK;
        const float coeff  = (rt == 2) ? LAMBDA_OCC : 1.0f;
        const float viol   = fmaxf(dA - dB + margin, 0.0f);

        total = coeff * conf[tid] * (valid ? 1.0f : 0.0f) * viol;
        count = valid ? 1.0f : 0.0f;
    }

    #pragma unroll
    for (int off = 16; off > 0; off >>= 1) {
        total += __shfl_xor_sync(0xFFFFFFFFu, total, off);
        count += __shfl_xor_sync(0xFFFFFFFFu, count, off);
    }
    __shared__ float sh_t[12], sh_n[12];
    if (lane == 0) { sh_t[wid] = total; sh_n[wid] = count; }
    __syncthreads();
    if (tid == 0) {
        float T = 0.0f, C = 0.0f;
        #pragma unroll
        for (int w = 0; w < 12; ++w) { T += sh_t[w]; C += sh_n[w]; }
        out[0] = (C > 0.0f) ? (T / fmaxf(C, 1.0f)) : 0.0f;
        g_ctr = 0;                        // reset for next graph replay
    }
}

extern "C" void kernel_launch(void* const* d_in, const int* in_sizes, int n_in,
                              void* d_out, int out_size)
{
    const float* depth = (const float*)d_in[0];
    const float* masks = (const float*)d_in[1];
    const int*   subj  = (const int*)  d_in[2];
    const int*   obj   = (const int*)  d_in[3];
    const int*   rel   = (const int*)  d_in[4];
    const float* conf  = (const float*)d_in[5];
    float*       out   = (float*)d_out;

    fused_kernel<<<NBLOCKS, NTHR>>>(depth, masks, subj, obj, rel, conf, out);
}

// round 15
// speedup vs baseline: 1.3282x; 1.3282x over previous
#include <cuda_runtime.h>
#include <cuda_bf16.h>
#include <cstdint>

// Problem dims (fixed by reference setup_inputs)
#define B_   4
#define N_   32
#define R_   64
#define H_   480
#define W_   640
#define HW_  (H_ * W_)         // 307200
#define NVEC (HW_ / 4)         // 76800 float4 per (b,n) slice
#define BN_  (B_ * N_)         // 128
#define BR_  (B_ * R_)         // 256

#define NGRP    8                    // n-values per block
#define GROUPS  (B_ * N_ / NGRP)     // 16
#define CHUNKS  37                   // 16*37 = 592 = 4*148 blocks, one balanced wave
#define NBLOCKS (GROUPS * CHUNKS)

#define T_F4       128               // float4 per array per tile (2KB)
#define NARR       10                // 8 masks + 2 depth copies (one per half-block)
#define STAGES     2
#define TILE_F4    (NARR * T_F4)     // 1280 f4 per stage
#define TILES_GRP  (NVEC / T_F4)     // 600 tiles per (b,n) group

#define MARGIN_RANK 0.1f
#define MARGIN_OCC  0.3f
#define LAMBDA_OCC  1.5f
#define MIN_PIXELS  20.0f

// Per-(chunk, bn) partials — each block owns its slots, no atomics needed.
__device__ float g_ps[CHUNKS * BN_];
__device__ float g_pc[CHUNKS * BN_];
__device__ unsigned int g_ctr = 0;   // last-block-done counter (self-resetting)

__device__ __forceinline__ uint32_t smem_u32(const void* p) {
    return (uint32_t)__cvta_generic_to_shared(p);
}
__device__ __forceinline__ void cp_async16(uint32_t dst, const void* src) {
    asm volatile("cp.async.cg.shared.global [%0], [%1], 16;\n" :: "r"(dst), "l"(src));
}
#define CP_COMMIT() asm volatile("cp.async.commit_group;\n" ::: "memory")
#define CP_WAIT(n)  asm volatile("cp.async.wait_group %0;\n" :: "n"(n) : "memory")

__global__ void __launch_bounds__(256, 4) fused_kernel(
    const float* __restrict__ depth,   // [B,1,H,W]
    const float* __restrict__ masks,   // [B,N,H,W]
    const int*   __restrict__ subj,
    const int*   __restrict__ obj,
    const int*   __restrict__ rel,
    const float* __restrict__ conf,
    float*       __restrict__ out)
{
    // [stage][array][T_F4] float4; arrays 0..7 = masks, 8/9 = depth copy for g=0/1
    __shared__ float4 tile[STAGES * TILE_F4];    // 40 KB

    const int tid   = threadIdx.x;
    const int g     = tid >> 7;            // half-block: 0 or 1
    const int e     = tid & 127;           // element lane within tile
    const int bx    = blockIdx.x;          // 0..591
    const int chunk = bx % CHUNKS;
    const int grp   = bx / CHUNKS;         // 0..15
    const int b     = grp >> 2;            // 4 groups per batch
    const int n0    = (grp & 3) * NGRP;

    const float4* __restrict__ dp = reinterpret_cast<const float4*>(depth)
                                    + (size_t)b * NVEC;
    const float4* __restrict__ mp = reinterpret_cast<const float4*>(masks)
                                    + (size_t)(b * N_ + n0) * NVEC;

    // Per-thread global sources: 4 mask arrays of parity g, plus depth.
    const float4* msrc[4];
    #pragma unroll
    for (int j = 0; j < 4; ++j)
        msrc[j] = mp + (size_t)(2 * j + g) * NVEC + e;
    const float4* dsrc = dp + e;

    // Per-thread smem destinations (2 stages x 5 slots), all privately owned.
    const uint32_t tile0 = smem_u32(&tile[0]);
    uint32_t dstm[STAGES][4], dstd[STAGES];
    #pragma unroll
    for (int st = 0; st < STAGES; ++st) {
        #pragma unroll
        for (int j = 0; j < 4; ++j)
            dstm[st][j] = tile0 + (uint32_t)((st * NARR + 2 * j + g) * T_F4 + e) * 16u;
        dstd[st] = tile0 + (uint32_t)((st * NARR + 8 + g) * T_F4 + e) * 16u;
    }

    // Tile range for this chunk (full tiles of 128 f4; 600 over 37 chunks)
    const int t0 = (chunk * TILES_GRP) / CHUNKS;
    const int t1 = ((chunk + 1) * TILES_GRP) / CHUNKS;
    const int nt = t1 - t0;

    float s[4], c[4];
    #pragma unroll
    for (int j = 0; j < 4; ++j) { s[j] = 0.0f; c[j] = 0.0f; }

    auto issue = [&](int st, int t) {
        const size_t o = (size_t)t * T_F4;
        #pragma unroll
        for (int j = 0; j < 4; ++j)
            cp_async16(dstm[st][j], msrc[j] + o);
        cp_async16(dstd[st], dsrc + o);
        CP_COMMIT();
    };

    // Prologue: tile 0 into stage 0
    issue(0, t0);

    // Barrier-free per-thread pipeline: issue tile k+1, wait for tile k, consume.
    for (int k = 0; k < nt; ++k) {
        if (k + 1 < nt) { issue((k + 1) & 1, t0 + k + 1); CP_WAIT(1); }
        else            { CP_WAIT(0); }

        const int cs = k & 1;
        const float4 d = tile[(cs * NARR + 8 + g) * T_F4 + e];
        #pragma unroll
        for (int j = 0; j < 4; ++j) {
            const float4 m = tile[(cs * NARR + 2 * j + g) * T_F4 + e];
            if (m.x > 0.5f) { s[j] += d.x; c[j] += 1.0f; }
            if (m.y > 0.5f) { s[j] += d.y; c[j] += 1.0f; }
            if (m.z > 0.5f) { s[j] += d.z; c[j] += 1.0f; }
            if (m.w > 0.5f) { s[j] += d.w; c[j] += 1.0f; }
        }
    }

    // ---- block reduce. Warp w covers parity g = w>>2; arrays a = 2j+g. ----
    #pragma unroll
    for (int j = 0; j < 4; ++j) {
        #pragma unroll
        for (int off = 16; off > 0; off >>= 1) {
            s[j] += __shfl_xor_sync(0xFFFFFFFFu, s[j], off);
            c[j] += __shfl_xor_sync(0xFFFFFFFFu, c[j], off);
        }
    }

    __shared__ float sh_s[8][4], sh_c[8][4];
    const int lane = tid & 31;
    const int wid  = tid >> 5;
    if (lane == 0) {
        #pragma unroll
        for (int j = 0; j < 4; ++j) { sh_s[wid][j] = s[j]; sh_c[wid][j] = c[j]; }
    }
    __syncthreads();

    if (tid < 2 * NGRP) {
        const int a  = tid & 7;            // array index 0..7
        const int j  = a >> 1;
        const int gg = a & 1;              // parity -> warps gg*4 .. gg*4+3
        float v = 0.0f;
        if (tid < NGRP) {
            #pragma unroll
            for (int w = 0; w < 4; ++w) v += sh_s[gg * 4 + w][j];
            g_ps[chunk * BN_ + b * N_ + n0 + a] = v;
        } else {
            #pragma unroll
            for (int w = 0; w < 4; ++w) v += sh_c[gg * 4 + w][j];
            g_pc[chunk * BN_ + b * N_ + n0 + a] = v;
        }
    }

    // ---- last-block-done: the final block runs the epilogue ----
    __shared__ bool is_last;
    __threadfence();
    __syncthreads();
    if (tid == 0) {
        unsigned int prev = atomicAdd(&g_ctr, 1u);
        is_last = (prev == NBLOCKS - 1);
    }
    __syncthreads();
    if (!is_last) return;
    __threadfence();

    // ===================== epilogue (one block, 256 threads) =====================
    __shared__ float sh_mean[BN_], sh_cnt[BN_];
    if (tid < BN_) {
        float sAcc = 0.0f, cAcc = 0.0f;
        #pragma unroll
        for (int ch = 0; ch < CHUNKS; ++ch) {
            sAcc += g_ps[ch * BN_ + tid];
            cAcc += g_pc[ch * BN_ + tid];
        }
        sh_mean[tid] = sAcc / fmaxf(cAcc, 1.0f);
        sh_cnt[tid]  = cAcc;
    }
    __syncthreads();

    const int bb_ = tid / R_;
    const int rt = rel[tid];
    const int si = subj[tid];
    const int oi = obj[tid];
    const int a  = (rt == 1) ? oi : si;
    const int bo = (rt == 1) ? si : oi;

    const float cntA = sh_cnt[bb_ * N_ + a];
    const float cntB = sh_cnt[bb_ * N_ + bo];
    const float dA   = sh_mean[bb_ * N_ + a];
    const float dB   = sh_mean[bb_ * N_ + bo];
    const bool  valid = (cntA >= MIN_PIXELS) && (cntB >= MIN_PIXELS);

    const float margin = (rt == 2) ? MARGIN_OCC : MARGIN_RANK;
    const float coeff  = (rt == 2) ? LAMBDA_OCC : 1.0f;
    const float viol   = fmaxf(dA - dB + margin, 0.0f);

    float total = coeff * conf[tid] * (valid ? 1.0f : 0.0f) * viol;
    float count = valid ? 1.0f : 0.0f;

    #pragma unroll
    for (int off = 16; off > 0; off >>= 1) {
        total += __shfl_xor_sync(0xFFFFFFFFu, total, off);
        count += __shfl_xor_sync(0xFFFFFFFFu, count, off);
    }
    __shared__ float sh_t[8], sh_n[8];
    if (lane == 0) { sh_t[wid] = total; sh_n[wid] = count; }
    __syncthreads();
    if (tid == 0) {
        float T = 0.0f, C = 0.0f;
        #pragma unroll
        for (int w = 0; w < 8; ++w) { T += sh_t[w]; C += sh_n[w]; }
        out[0] = (C > 0.0f) ? (T / fmaxf(C, 1.0f)) : 0.0f;
        g_ctr = 0;                        // reset for next graph replay
    }
}

extern "C" void kernel_launch(void* const* d_in, const int* in_sizes, int n_in,
                              void* d_out, int out_size)
{
    const float* depth = (const float*)d_in[0];
    const float* masks = (const float*)d_in[1];
    const int*   subj  = (const int*)  d_in[2];
    const int*   obj   = (const int*)  d_in[3];
    const int*   rel   = (const int*)  d_in[4];
    const float* conf  = (const float*)d_in[5];
    float*       out   = (float*)d_out;

    fused_kernel<<<NBLOCKS, 256>>>(depth, masks, subj, obj, rel, conf, out);
}

// round 17
// speedup vs baseline: 1.4876x; 1.1201x over previous
#include <cuda_runtime.h>
#include <cuda_bf16.h>
#include <cstdint>

// Problem dims (fixed by reference setup_inputs)
#define B_   4
#define N_   32
#define R_   64
#define H_   480
#define W_   640
#define HW_  (H_ * W_)         // 307200
#define NVEC (HW_ / 4)         // 76800 float4 per (b,n) slice
#define BN_  (B_ * N_)         // 128
#define BR_  (B_ * R_)         // 256
#define TOTF4 (BN_ * NVEC)     // 9,830,400 float4 in masks

#define NBLOCKS 592            // 4 * 148 -> one perfectly balanced wave

#define MARGIN_RANK 0.1f
#define MARGIN_OCC  0.3f
#define LAMBDA_OCC  1.5f
#define MIN_PIXELS  20.0f

// Global accumulators (atomic). Zeroed at static init; the epilogue re-zeros
// them after each use so graph replays see a clean state.
__device__ float g_sum[BN_];
__device__ float g_cnt[BN_];
__device__ unsigned int g_ctr = 0;   // last-block-done counter (self-resetting)

__global__ void __launch_bounds__(256) fused_kernel(
    const float* __restrict__ depth,   // [B,1,H,W]
    const float* __restrict__ masks,   // [B,N,H,W]
    const int*   __restrict__ subj,
    const int*   __restrict__ obj,
    const int*   __restrict__ rel,
    const float* __restrict__ conf,
    float*       __restrict__ out)
{
    const int tid = threadIdx.x;
    const int bx  = blockIdx.x;

    // Contiguous flat range of the masks tensor for this block (f4 units).
    int f0 = (int)(((long long)bx       * TOTF4) / NBLOCKS);
    const int f1 = (int)(((long long)(bx + 1) * TOTF4) / NBLOCKS);

    const float4* __restrict__ mflat = reinterpret_cast<const float4*>(masks);
    const float4* __restrict__ dflat = reinterpret_cast<const float4*>(depth);

    const int lane = tid & 31;

    int sl = f0 / NVEC;                       // current (b,n) slice
    while (f0 < f1) {
        const int send = min(f1, (sl + 1) * NVEC);
        const int cnt  = send - f0;
        const int b    = sl >> 5;             // sl / N_

        const float4* __restrict__ mB = mflat + f0;
        const float4* __restrict__ dB = dflat + (size_t)b * NVEC + (f0 - sl * NVEC);

        float s = 0.0f, c = 0.0f;
        #pragma unroll 4
        for (int i = tid; i < cnt; i += 256) {
            const float4 m = __ldcs(&mB[i]);  // streaming: evict-first
            const float4 d = dB[i];           // L2-resident (4.9 MB, reused 32x)
            if (m.x > 0.5f) { s += d.x; c += 1.0f; }
            if (m.y > 0.5f) { s += d.y; c += 1.0f; }
            if (m.z > 0.5f) { s += d.z; c += 1.0f; }
            if (m.w > 0.5f) { s += d.w; c += 1.0f; }
        }

        // Warp reduce, then one atomic pair per warp per sub-range.
        #pragma unroll
        for (int off = 16; off > 0; off >>= 1) {
            s += __shfl_xor_sync(0xFFFFFFFFu, s, off);
            c += __shfl_xor_sync(0xFFFFFFFFu, c, off);
        }
        if (lane == 0) {
            atomicAdd(&g_sum[sl], s);
            atomicAdd(&g_cnt[sl], c);
        }

        f0 = send;
        ++sl;
    }

    // ---- last-block-done: the final block runs the epilogue ----
    __shared__ bool is_last;
    __threadfence();
    __syncthreads();
    if (tid == 0) {
        unsigned int prev = atomicAdd(&g_ctr, 1u);
        is_last = (prev == NBLOCKS - 1);
    }
    __syncthreads();
    if (!is_last) return;
    __threadfence();

    // ===================== epilogue (one block, 256 threads) =====================
    __shared__ float sh_mean[BN_], sh_cnt[BN_];
    if (tid < BN_) {
        const float cAcc = g_cnt[tid];
        sh_mean[tid] = g_sum[tid] / fmaxf(cAcc, 1.0f);
        sh_cnt[tid]  = cAcc;
    }
    __syncthreads();

    // Reset accumulators for the next graph replay (after all reads above).
    if (tid < BN_) { g_sum[tid] = 0.0f; g_cnt[tid] = 0.0f; }

    const int bb_ = tid / R_;
    const int rt = rel[tid];
    const int si = subj[tid];
    const int oi = obj[tid];
    const int a  = (rt == 1) ? oi : si;
    const int bo = (rt == 1) ? si : oi;

    const float cntA = sh_cnt[bb_ * N_ + a];
    const float cntB = sh_cnt[bb_ * N_ + bo];
    const float dA   = sh_mean[bb_ * N_ + a];
    const float dB   = sh_mean[bb_ * N_ + bo];
    const bool  valid = (cntA >= MIN_PIXELS) && (cntB >= MIN_PIXELS);

    const float margin = (rt == 2) ? MARGIN_OCC : MARGIN_RANK;
    const float coeff  = (rt == 2) ? LAMBDA_OCC : 1.0f;
    const float viol   = fmaxf(dA - dB + margin, 0.0f);

    float total = coeff * conf[tid] * (valid ? 1.0f : 0.0f) * viol;
    float count = valid ? 1.0f : 0.0f;

    #pragma unroll
    for (int off = 16; off > 0; off >>= 1) {
        total += __shfl_xor_sync(0xFFFFFFFFu, total, off);
        count += __shfl_xor_sync(0xFFFFFFFFu, count, off);
    }
    __shared__ float sh_t[8], sh_n[8];
    const int wid = tid >> 5;
    if (lane == 0) { sh_t[wid] = total; sh_n[wid] = count; }
    __syncthreads();
    if (tid == 0) {
        float T = 0.0f, C = 0.0f;
        #pragma unroll
        for (int w = 0; w < 8; ++w) { T += sh_t[w]; C += sh_n[w]; }
        out[0] = (C > 0.0f) ? (T / fmaxf(C, 1.0f)) : 0.0f;
        g_ctr = 0;                        // reset for next graph replay
    }
}

extern "C" void kernel_launch(void* const* d_in, const int* in_sizes, int n_in,
                              void* d_out, int out_size)
{
    const float* depth = (const float*)d_in[0];
    const float* masks = (const float*)d_in[1];
    const int*   subj  = (const int*)  d_in[2];
    const int*   obj   = (const int*)  d_in[3];
    const int*   rel   = (const int*)  d_in[4];
    const float* conf  = (const float*)d_in[5];
    float*       out   = (float*)d_out;

    fused_kernel<<<NBLOCKS, 256>>>(depth, masks, subj, obj, rel, conf, out);
}